// round 7
// baseline (speedup 1.0000x reference)
#include <cuda_runtime.h>
#include <cuda_fp16.h>

typedef unsigned long long u64;
typedef unsigned int u32;

#define K_CODES 8192
#define EDIM 128
#define TM 128
#define TN 128
#define N_TILES (K_CODES / TN)    // 64
#define SAH 136                   // padded row stride (halfs)
#define SAW 68                    // row stride in 32-bit words
#define A_BYTES (128 * SAH * 2)   // 34816
#define STAGE_BYTES (128 * SAH * 2)
#define ZS_OFF (3 * A_BYTES)                 // float[128]
#define SB_OFF (ZS_OFF + 512)                // u64[128]
#define SMEM_TOTAL (120 * 1024)              // padded: force 1 CTA/SM
#define DELTA 3e-3f

__device__ float  d_esq[K_CODES];
__device__ float  d_zsq[32768];
__device__ __align__(16) u32 d_emb_h[K_CODES * 64];   // fp16 image of emb
__device__ int    d_counts[K_CODES];
__device__ int    d_idx[32768];
__device__ u64    d_minkey[32768];
__device__ u64    d_cand[32768 * 32];
__device__ double d_sumsq;

// ---------------- helpers ----------------
__device__ __forceinline__ u32 smem_u32(const void* p) {
    u32 a; asm("{ .reg .u64 t; cvta.to.shared.u64 t, %1; cvt.u32.u64 %0, t; }" : "=r"(a) : "l"(p));
    return a;
}
__device__ __forceinline__ u32 fkey(float s) {
    u32 b = __float_as_uint(s);
    return (b & 0x80000000u) ? ~b : (b | 0x80000000u);
}
__device__ __forceinline__ float unfkey(u32 k) {
    u32 b = (k & 0x80000000u) ? (k & 0x7FFFFFFFu) : ~k;
    return __uint_as_float(b);
}
__device__ __forceinline__ void cp16(u32 dst, const void* src) {
    asm volatile("cp.async.cg.shared.global [%0], [%1], 16;" :: "r"(dst), "l"(src) : "memory");
}
// f16-accumulate MMA: D,C in f16 (possible 2x rate vs f32 acc)
__device__ __forceinline__ void mma16h(u32* c, const u32* a, const u32* b) {
    asm volatile(
        "mma.sync.aligned.m16n8k16.row.col.f16.f16.f16.f16 "
        "{%0,%1}, {%2,%3,%4,%5}, {%6,%7}, {%0,%1};"
        : "+r"(c[0]), "+r"(c[1])
        : "r"(a[0]), "r"(a[1]), "r"(a[2]), "r"(a[3]), "r"(b[0]), "r"(b[1]));
}
__device__ __forceinline__ void ldsm4(u32* r, u32 addr) {
    asm volatile("ldmatrix.sync.aligned.m8n8.x4.shared.b16 {%0,%1,%2,%3}, [%4];"
        : "=r"(r[0]), "=r"(r[1]), "=r"(r[2]), "=r"(r[3]) : "r"(addr));
}
__device__ __forceinline__ u32 h2u(float x, float y) {
    __half2 h = __floats2half2_rn(x, y);
    return *(u32*)&h;
}
__device__ __forceinline__ void top2(u64& b1, u64& b2, u64 k) {
    if (k < b1) { b2 = b1; b1 = k; }
    else if (k < b2) { b2 = k; }
}

// ---------- kernel 0: |e_k|^2, fp16 emb image, zero counts/sumsq ----------
__global__ void k_init(const float* __restrict__ emb) {
    int k = blockIdx.x * blockDim.x + threadIdx.x;
    if (k < K_CODES) {
        const float4* row = (const float4*)(emb + (size_t)k * EDIM);
        float s = 0.f;
#pragma unroll
        for (int i = 0; i < EDIM / 4; i++) {
            float4 v = row[i];
            s += v.x * v.x + v.y * v.y + v.z * v.z + v.w * v.w;
            d_emb_h[k * 64 + i * 2]     = h2u(v.x, v.y);
            d_emb_h[k * 64 + i * 2 + 1] = h2u(v.z, v.w);
        }
        d_esq[k] = s;
        d_counts[k] = 0;
    }
    if (blockIdx.x == 0 && threadIdx.x == 0) d_sumsq = 0.0;
}

// ---------- main: fp16 screening GEMM (f16 acc, ldmatrix) + top-2 ----------
extern "C" __global__ void __launch_bounds__(256, 1)
k_main(const float* __restrict__ z, const float* __restrict__ emb) {
    extern __shared__ char smem[];
    u32*   A32   = (u32*)smem;                        // [128][68] half2 words
    float* zsmem = (float*)(smem + ZS_OFF);           // [128]
    u64*   sbest = (u64*)(smem + SB_OFF);             // [128]

    const int tid  = threadIdx.x;
    const int wid  = tid >> 5;
    const int lane = tid & 31;
    const int lr   = lane >> 2;
    const int lc   = lane & 3;
    const int wm   = (wid & 1) * 64;
    const int wn   = (wid >> 1) * 32;
    const int rowBase = blockIdx.x * TM;

    const u32 smb   = smem_u32(smem);
    const u32 bsOff = smb + A_BYTES;

    // ldmatrix base addresses (byte smem offsets), kb adds 32B per step
    u32 aBase[4], bBase[2];
#pragma unroll
    for (int i = 0; i < 4; i++)
        aBase[i] = smb + ((u32)((wm + i * 16 + ((lane >> 3) & 1) * 8 + (lane & 7)) * SAW
                   + (lane >> 4) * 4)) * 4;
#pragma unroll
    for (int jj = 0; jj < 2; jj++)
        bBase[jj] = (u32)((wn + jj * 16 + ((lane >> 4) & 1) * 8 + (lane & 7)) * SAW
                   + ((lane >> 3) & 1) * 4) * 4;

    // prefetch tile 0 (fp16 image: 16B chunks)
    {
#pragma unroll
        for (int i = 0; i < 8; i++) {
            int idx = tid + i * 256;
            int r = idx >> 4, seg = idx & 15;
            cp16(bsOff + (u32)(r * (SAH * 2) + seg * 16), d_emb_h + r * 64 + seg * 4);
        }
        asm volatile("cp.async.commit_group;" ::: "memory");
    }

    // prologue: zsq (exact, round-2-identical order), As = fp16(z)
    if (tid < 128) {
        const float4* zr = (const float4*)(z + (size_t)(rowBase + tid) * EDIM);
        float s = 0.f;
#pragma unroll
        for (int q = 0; q < 32; q++) {
            float4 v = zr[q];
            s += v.x * v.x + v.y * v.y + v.z * v.z + v.w * v.w;
            A32[tid * SAW + q * 2]     = h2u(v.x, v.y);
            A32[tid * SAW + q * 2 + 1] = h2u(v.z, v.w);
        }
        d_zsq[rowBase + tid] = s;
        zsmem[tid] = s;
        sbest[tid] = ~0ULL;
    }
    __syncthreads();

    float zrow[4][2];
#pragma unroll
    for (int i = 0; i < 4; i++) {
        zrow[i][0] = zsmem[wm + i * 16 + lr];
        zrow[i][1] = zsmem[wm + i * 16 + lr + 8];
    }

    u64 best1[4][2], best2[4][2];
#pragma unroll
    for (int i = 0; i < 4; i++)
#pragma unroll
        for (int s = 0; s < 2; s++) { best1[i][s] = ~0ULL; best2[i][s] = ~0ULL; }

#pragma unroll 1
    for (int tile = 0; tile < N_TILES; tile++) {
        const int st = tile & 1;
        const int colBase = tile * TN;

        float eq[4][2];
#pragma unroll
        for (int j = 0; j < 4; j++) {
            int c0 = colBase + wn + j * 8 + 2 * lc;
            eq[j][0] = d_esq[c0];
            eq[j][1] = d_esq[c0 + 1];
        }

        if (tile + 1 < N_TILES) {
            const u32* src = d_emb_h + (size_t)(colBase + TN) * 64;
            u32 dstb = bsOff + (st ^ 1) * STAGE_BYTES;
#pragma unroll
            for (int i = 0; i < 8; i++) {
                int idx = tid + i * 256;
                int r = idx >> 4, seg = idx & 15;
                cp16(dstb + (u32)(r * (SAH * 2) + seg * 16), src + r * 64 + seg * 4);
            }
            asm volatile("cp.async.commit_group;" ::: "memory");
            asm volatile("cp.async.wait_group 1;" ::: "memory");
        } else {
            asm volatile("cp.async.wait_group 0;" ::: "memory");
        }
        __syncthreads();

        const u32 bSt = bsOff + st * STAGE_BYTES;

        u32 acc[4][4][2];
#pragma unroll
        for (int i = 0; i < 4; i++)
#pragma unroll
            for (int j = 0; j < 4; j++) { acc[i][j][0] = 0u; acc[i][j][1] = 0u; }

#pragma unroll
        for (int kb = 0; kb < 8; kb++) {
            const u32 kOff = (u32)kb * 32;            // 8 words = 32 bytes
            u32 af[4][4], bf[2][4];
#pragma unroll
            for (int i = 0; i < 4; i++) ldsm4(af[i], aBase[i] + kOff);
#pragma unroll
            for (int jj = 0; jj < 2; jj++) ldsm4(bf[jj], bSt + bBase[jj] + kOff);
#pragma unroll
            for (int i = 0; i < 4; i++) {
                mma16h(acc[i][0], af[i], &bf[0][0]);
                mma16h(acc[i][1], af[i], &bf[0][2]);
                mma16h(acc[i][2], af[i], &bf[1][0]);
                mma16h(acc[i][3], af[i], &bf[1][2]);
            }
        }

        // approx epilogue: grid formula on unpacked f16 sums, top-2 per thread
#pragma unroll
        for (int i = 0; i < 4; i++) {
#pragma unroll
            for (int j = 0; j < 4; j++) {
                int cg0 = colBase + wn + j * 8 + 2 * lc;
                float2 g0 = __half22float2(*(__half2*)&acc[i][j][0]);  // row lr
                float2 g1 = __half22float2(*(__half2*)&acc[i][j][1]);  // row lr+8
                {
                    float t0 = zrow[i][0] + eq[j][0];
                    float t1 = zrow[i][0] + eq[j][1];
                    float d0 = t0 - 2.f * g0.x;
                    float d1 = t1 - 2.f * g0.y;
                    top2(best1[i][0], best2[i][0], ((u64)fkey(d0) << 13) | (u32)cg0);
                    top2(best1[i][0], best2[i][0], ((u64)fkey(d1) << 13) | (u32)(cg0 + 1));
                }
                {
                    float t0 = zrow[i][1] + eq[j][0];
                    float t1 = zrow[i][1] + eq[j][1];
                    float d0 = t0 - 2.f * g1.x;
                    float d1 = t1 - 2.f * g1.y;
                    top2(best1[i][1], best2[i][1], ((u64)fkey(d0) << 13) | (u32)cg0);
                    top2(best1[i][1], best2[i][1], ((u64)fkey(d1) << 13) | (u32)(cg0 + 1));
                }
            }
        }
        __syncthreads();
    }

    const int slot = (wid >> 1) * 4 + lc;             // 0..15 per row
#pragma unroll
    for (int i = 0; i < 4; i++)
#pragma unroll
        for (int s = 0; s < 2; s++) {
            int rl = wm + i * 16 + lr + s * 8;
            atomicMin(&sbest[rl], best1[i][s]);
            u64* c = &d_cand[(size_t)(rowBase + rl) * 32 + slot * 2];
            c[0] = best1[i][s];
            c[1] = best2[i][s];
        }
    __syncthreads();
    if (tid < 128) d_minkey[rowBase + tid] = sbest[tid];
}

// ---------- rescore: exact fp32 dot on candidates, grid-exact argmin ----------
__global__ void k_rescore(const float* __restrict__ z, const float* __restrict__ emb) {
    int warp = (blockIdx.x * blockDim.x + threadIdx.x) >> 5;
    int lane = threadIdx.x & 31;
    int r = warp;

    u64 key = d_cand[(size_t)r * 32 + lane];
    u64 mk  = d_minkey[r];
    float dmin = unfkey((u32)(mk >> 13));
    u32 thr = fkey(dmin + DELTA);

    u64 mykey = ~0ULL;
    if ((u32)(key >> 13) <= thr) {
        int idx = (int)(key & 0x1FFFULL);
        const float4* zr = (const float4*)(z + (size_t)r * EDIM);
        const float4* er = (const float4*)(emb + (size_t)idx * EDIM);
        float dot = 0.f;
#pragma unroll
        for (int q = 0; q < 32; q++) {
            float4 a = zr[q], b = er[q];
            dot += a.x * b.x + a.y * b.y + a.z * b.z + a.w * b.w;
        }
        float t = d_zsq[r] + d_esq[idx];              // fl(zsq+esq)
        float d = t - 2.f * dot;                      // fl(t - 2*dot): grid-exact
        mykey = ((u64)fkey(d) << 13) | (u32)idx;
    }
#pragma unroll
    for (int off = 16; off; off >>= 1) {
        u64 o = __shfl_xor_sync(0xffffffffu, mykey, off);
        if (o < mykey) mykey = o;
    }
    if (lane == 0) d_idx[r] = (int)(mykey & 0x1FFFULL);
}

// ---------- gather + straight-through out + sums + counts ----------
__global__ void k_gather(const float* __restrict__ z, const float* __restrict__ emb,
                         float* __restrict__ out) {
    __shared__ float red[8];
    int e4 = blockIdx.x * blockDim.x + threadIdx.x;
    int row = e4 >> 5;
    int d4  = e4 & 31;
    int k = d_idx[row];
    float4 q  = ((const float4*)(emb + (size_t)k * EDIM))[d4];
    float4 zz = ((const float4*)z)[e4];
    float4 o;
    float s = 0.f, df;
    df = q.x - zz.x; o.x = zz.x + df; s += df * df;
    df = q.y - zz.y; o.y = zz.y + df; s += df * df;
    df = q.z - zz.z; o.z = zz.z + df; s += df * df;
    df = q.w - zz.w; o.w = zz.w + df; s += df * df;
    ((float4*)out)[e4] = o;
    if (d4 == 0) atomicAdd(&d_counts[k], 1);
#pragma unroll
    for (int off = 16; off; off >>= 1) s += __shfl_xor_sync(0xffffffffu, s, off);
    int lane = threadIdx.x & 31, w = threadIdx.x >> 5;
    if (lane == 0) red[w] = s;
    __syncthreads();
    if (threadIdx.x == 0) {
        float bs = 0.f;
#pragma unroll
        for (int i = 0; i < 8; i++) bs += red[i];
        atomicAdd(&d_sumsq, (double)bs);
    }
}

// ---------- perplexity + commit loss ----------
__global__ void k_final(float* __restrict__ out, int n_rows) {
    __shared__ float red[256];
    float acc = 0.f;
    float invN = 1.f / (float)n_rows;
    for (int k = threadIdx.x; k < K_CODES; k += 256) {
        float e = (float)d_counts[k] * invN;
        acc += e * logf(e + 1e-8f);
    }
    red[threadIdx.x] = acc;
    __syncthreads();
    for (int s = 128; s; s >>= 1) {
        if (threadIdx.x < s) red[threadIdx.x] += red[threadIdx.x + s];
        __syncthreads();
    }
    if (threadIdx.x == 0) {
        float m = (float)(d_sumsq / (double)((size_t)n_rows * EDIM));
        out[(size_t)n_rows * EDIM]     = 0.25f * m + m;
        out[(size_t)n_rows * EDIM + 1] = expf(-red[0]);
    }
}

extern "C" void kernel_launch(void* const* d_in, const int* in_sizes, int n_in,
                              void* d_out, int out_size) {
    const float* z   = (const float*)d_in[0];
    const float* emb = (const float*)d_in[1];
    float* out = (float*)d_out;
    int n_rows = in_sizes[0] / EDIM;                  // 32768

    cudaFuncSetAttribute(k_main, cudaFuncAttributeMaxDynamicSharedMemorySize, SMEM_TOTAL);

    k_init<<<K_CODES / 256, 256>>>(emb);
    k_main<<<n_rows / TM, 256, SMEM_TOTAL>>>(z, emb);
    k_rescore<<<n_rows / 8, 256>>>(z, emb);
    k_gather<<<(n_rows * (EDIM / 4)) / 256, 256>>>(z, emb, out);
    k_final<<<1, 256>>>(out, n_rows);
}